// round 6
// baseline (speedup 1.0000x reference)
#include <cuda_runtime.h>
#include <cuda_bf16.h>

#define SS 7
#define NCH 25
#define MAXCELLS 8192
#define LAMBDA_COORD 5.0f
#define LAMBDA_NOOBJ 0.5f
#define EPS_SQRT 1e-6f
#define EPS_IOU 1e-10f
#define TPB 128
#define NWARP (TPB / 32)
#define MAXBLK 128

// __device__ globals (zero-init; kernel self-resets -> identical on every replay)
__device__ double g_part [MAXBLK];
__device__ double g_part2[MAXBLK];
__device__ int    g_cnt   = 0;
__device__ int    g_done1 = 0;
__device__ int    g_done2 = 0;
// compacted per-object-cell data: target corners+area, pred corners+area+conf
__device__ float  g_tx1[MAXCELLS], g_ty1[MAXCELLS], g_tx2[MAXCELLS], g_ty2[MAXCELLS], g_ta[MAXCELLS];
__device__ float  g_px1[MAXCELLS], g_py1[MAXCELLS], g_px2[MAXCELLS], g_py2[MAXCELLS], g_pa[MAXCELLS], g_pc[MAXCELLS];

__global__ void __launch_bounds__(TPB)
k_yolo_coop(const float* __restrict__ pred,
            const float* __restrict__ targ,
            float* __restrict__ out,
            int M, int nblocks, float invB) {
    const int tid  = threadIdx.x;
    const int lane = tid & 31;
    const int wid  = tid >> 5;
    const int i    = blockIdx.x * TPB + tid;   // owned cell

    __shared__ int s_wbase[NWARP];
    __shared__ int s_cnt, s_gbase;
    __shared__ double swred[NWARP];
    if (tid == 0) s_cnt = 0;
    __syncthreads();

    // ---------------- Phase 1: own-cell losses + global compaction ----------
    double local = 0.0;
    bool isObj = false;
    float px1=0.f, py1=0.f, px2=0.f, py2=0.f, pa=0.f, pc=0.f;
    float tx1=0.f, ty1=0.f, tx2=0.f, ty2=0.f, ta=0.f;

    if (i < M) {
        const float* pp = pred + (size_t)i * NCH;
        const float* tt = targ + (size_t)i * NCH;
        float t4 = tt[4];
        pc = pp[4];
        if (t4 > 0.0f) {
            isObj = true;
            float dx = pp[0] - tt[0];
            float dy = pp[1] - tt[1];
            float sw = sqrtf(pp[2] + EPS_SQRT) - sqrtf(tt[2] + EPS_SQRT);
            float sh = sqrtf(pp[3] + EPS_SQRT) - sqrtf(tt[3] + EPS_SQRT);
            float cl = 0.0f;
            #pragma unroll
            for (int c = 5; c < NCH; c++) {
                float d = pp[c] - tt[c];
                cl += d * d;
            }
            local += (double)(LAMBDA_COORD * (dx*dx + dy*dy + sw*sw + sh*sh) + cl);
            float cx = pp[0], cy = pp[1], w = pp[2], h = pp[3];
            px1 = cx - w*0.5f;  py1 = cy - h*0.5f;
            px2 = cx + w*0.5f;  py2 = cy + h*0.5f;
            pa  = (px2 - px1) * (py2 - py1);
            cx = tt[0]; cy = tt[1]; w = tt[2]; h = tt[3];
            tx1 = cx - w*0.5f;  ty1 = cy - h*0.5f;
            tx2 = cx + w*0.5f;  ty2 = cy + h*0.5f;
            ta  = (tx2 - tx1) * (ty2 - ty1);
        } else {
            local += (double)(LAMBDA_NOOBJ * pc * pc);
        }
    }

    // warp -> block -> one global atomic for compaction offsets
    unsigned m = __ballot_sync(0xffffffffu, isObj);
    int nobj = __popc(m);
    if (lane == 0) s_wbase[wid] = (nobj > 0) ? atomicAdd(&s_cnt, nobj) : 0;
    __syncthreads();
    if (tid == 0) s_gbase = (s_cnt > 0) ? atomicAdd(&g_cnt, s_cnt) : 0;
    __syncthreads();
    if (isObj) {
        int pos = s_gbase + s_wbase[wid] + __popc(m & ((1u << lane) - 1));
        g_tx1[pos]=tx1; g_ty1[pos]=ty1; g_tx2[pos]=tx2; g_ty2[pos]=ty2; g_ta[pos]=ta;
        g_px1[pos]=px1; g_py1[pos]=py1; g_px2[pos]=px2; g_py2[pos]=py2; g_pa[pos]=pa; g_pc[pos]=pc;
    }

    // block reduce phase-1 losses
    #pragma unroll
    for (int off = 16; off > 0; off >>= 1)
        local += __shfl_down_sync(0xffffffffu, local, off);
    if (lane == 0) swred[wid] = local;
    __syncthreads();
    if (wid == 0) {
        double v = (lane < NWARP) ? swred[lane] : 0.0;
        #pragma unroll
        for (int off = NWARP >> 1; off > 0; off >>= 1)
            v += __shfl_down_sync(0xffffffffu, v, off);
        if (lane == 0) g_part[blockIdx.x] = v;
    }

    // ---------------- Grid barrier (all 49 blocks co-resident) --------------
    __threadfence();
    __syncthreads();
    if (tid == 0) atomicAdd(&g_done1, 1);
    if (tid == 0) {
        volatile int* vd = &g_done1;
        while (*vd < nblocks) { }
    }
    __syncthreads();
    __threadfence();

    const int K = g_cnt;

    // ---------------- Phase 2: warp-per-object-cell conf loss ---------------
    double l2 = 0.0;
    const int gwarp  = blockIdx.x * NWARP + wid;
    const int nwarps = nblocks * NWARP;
    for (int c = gwarp; c < K; c += nwarps) {
        float bx1 = g_px1[c], by1 = g_py1[c], bx2 = g_px2[c], by2 = g_py2[c];
        float ba  = g_pa[c],  bpc = g_pc[c];
        float best = -1.0f;
        for (int j = lane; j < K; j += 32) {
            float iw = fminf(bx2, g_tx2[j]) - fmaxf(bx1, g_tx1[j]);
            float ih = fminf(by2, g_ty2[j]) - fmaxf(by1, g_ty1[j]);
            iw = fmaxf(iw, 0.0f);
            ih = fmaxf(ih, 0.0f);
            float inter = iw * ih;
            float iou = __fdividef(inter, ba + g_ta[j] - inter + EPS_IOU);
            best = fmaxf(best, iou);
        }
        #pragma unroll
        for (int off = 16; off > 0; off >>= 1)
            best = fmaxf(best, __shfl_xor_sync(0xffffffffu, best, off));
        if (lane == 0) {
            float d = bpc - best;
            l2 += (double)(d * d);
        }
    }

    // block reduce phase-2 losses (only lane 0 of each warp holds data)
    if (lane == 0) swred[wid] = l2;
    __syncthreads();
    if (wid == 0) {
        double v = (lane < NWARP) ? swred[lane] : 0.0;
        #pragma unroll
        for (int off = NWARP >> 1; off > 0; off >>= 1)
            v += __shfl_down_sync(0xffffffffu, v, off);
        if (lane == 0) g_part2[blockIdx.x] = v;
    }

    // ---------------- Last block finalizes + resets --------------------------
    __threadfence();
    __syncthreads();
    __shared__ int is_last;
    if (tid == 0) is_last = (atomicAdd(&g_done2, 1) == nblocks - 1) ? 1 : 0;
    __syncthreads();
    if (!is_last) return;

    if (tid == 0) {
        double tot = 0.0;
        for (int b = 0; b < nblocks; b++) tot += g_part[b] + g_part2[b];
        out[0] = (float)(tot * (double)invB);
        g_cnt   = 0;   // reset for next graph replay (all blocks already past both barriers)
        g_done1 = 0;
        g_done2 = 0;
    }
}

extern "C" void kernel_launch(void* const* d_in, const int* in_sizes, int n_in,
                              void* d_out, int out_size) {
    const float* pred = (const float*)d_in[0];
    const float* targ = (const float*)d_in[1];
    float* out = (float*)d_out;

    int total = in_sizes[0];           // B * S * S * N
    int M = total / NCH;               // 6272 cells
    int B = M / (SS * SS);
    float invB = 1.0f / (float)B;

    int nblocks = (M + TPB - 1) / TPB; // 49  (co-resident: 49 < #SMs)
    k_yolo_coop<<<nblocks, TPB>>>(pred, targ, out, M, nblocks, invB);
}

// round 7
// speedup vs baseline: 1.1029x; 1.1029x over previous
#include <cuda_runtime.h>
#include <cuda_bf16.h>

#define SS 7
#define NCH 25
#define MAXCELLS 8192
#define LAMBDA_COORD 5.0f
#define LAMBDA_NOOBJ 0.5f
#define EPS_SQRT 1e-6f
#define EPS_IOU 1e-10f
#define TPB 1024
#define NWARP (TPB / 32)

// __device__ globals (zero-init; kernel self-resets -> identical on every replay)
__device__ double g_acc1  = 0.0;   // phase-1 loss accumulator
__device__ double g_acc2  = 0.0;   // phase-2 loss accumulator
__device__ int    g_cnt   = 0;
__device__ int    g_done1 = 0;
__device__ int    g_done2 = 0;
// compacted per-object-cell data: target corners+area, pred corners+area+conf
__device__ float  g_tx1[MAXCELLS], g_ty1[MAXCELLS], g_tx2[MAXCELLS], g_ty2[MAXCELLS], g_ta[MAXCELLS];
__device__ float  g_px1[MAXCELLS], g_py1[MAXCELLS], g_px2[MAXCELLS], g_py2[MAXCELLS], g_pa[MAXCELLS], g_pc[MAXCELLS];

__global__ void __launch_bounds__(TPB)
k_yolo_coop(const float* __restrict__ pred,
            const float* __restrict__ targ,
            float* __restrict__ out,
            int M, int nblocks, float invB) {
    const int tid  = threadIdx.x;
    const int lane = tid & 31;
    const int wid  = tid >> 5;
    const int i    = blockIdx.x * TPB + tid;   // owned cell (one per thread)

    __shared__ int s_wbase[NWARP];
    __shared__ int s_cnt, s_gbase;
    __shared__ double swred[NWARP];
    if (tid == 0) s_cnt = 0;
    __syncthreads();

    // ---------------- Phase 1: own-cell losses + global compaction ----------
    double local = 0.0;
    bool isObj = false;
    float px1=0.f, py1=0.f, px2=0.f, py2=0.f, pa=0.f, pc=0.f;
    float tx1=0.f, ty1=0.f, tx2=0.f, ty2=0.f, ta=0.f;

    if (i < M) {
        const float* pp = pred + (size_t)i * NCH;
        const float* tt = targ + (size_t)i * NCH;
        float t4 = tt[4];
        pc = pp[4];
        if (t4 > 0.0f) {
            isObj = true;
            float dx = pp[0] - tt[0];
            float dy = pp[1] - tt[1];
            float sw = sqrtf(pp[2] + EPS_SQRT) - sqrtf(tt[2] + EPS_SQRT);
            float sh = sqrtf(pp[3] + EPS_SQRT) - sqrtf(tt[3] + EPS_SQRT);
            float cl = 0.0f;
            #pragma unroll
            for (int c = 5; c < NCH; c++) {
                float d = pp[c] - tt[c];
                cl += d * d;
            }
            local += (double)(LAMBDA_COORD * (dx*dx + dy*dy + sw*sw + sh*sh) + cl);
            float cx = pp[0], cy = pp[1], w = pp[2], h = pp[3];
            px1 = cx - w*0.5f;  py1 = cy - h*0.5f;
            px2 = cx + w*0.5f;  py2 = cy + h*0.5f;
            pa  = (px2 - px1) * (py2 - py1);
            cx = tt[0]; cy = tt[1]; w = tt[2]; h = tt[3];
            tx1 = cx - w*0.5f;  ty1 = cy - h*0.5f;
            tx2 = cx + w*0.5f;  ty2 = cy + h*0.5f;
            ta  = (tx2 - tx1) * (ty2 - ty1);
        } else {
            local += (double)(LAMBDA_NOOBJ * pc * pc);
        }
    }

    // warp -> block -> one global atomic for compaction offsets
    unsigned m = __ballot_sync(0xffffffffu, isObj);
    int nobj = __popc(m);
    if (lane == 0) s_wbase[wid] = (nobj > 0) ? atomicAdd(&s_cnt, nobj) : 0;
    __syncthreads();
    if (tid == 0) s_gbase = (s_cnt > 0) ? atomicAdd(&g_cnt, s_cnt) : 0;
    __syncthreads();
    if (isObj) {
        int pos = s_gbase + s_wbase[wid] + __popc(m & ((1u << lane) - 1));
        g_tx1[pos]=tx1; g_ty1[pos]=ty1; g_tx2[pos]=tx2; g_ty2[pos]=ty2; g_ta[pos]=ta;
        g_px1[pos]=px1; g_py1[pos]=py1; g_px2[pos]=px2; g_py2[pos]=py2; g_pa[pos]=pa; g_pc[pos]=pc;
    }

    // block reduce phase-1 losses -> single double atomic
    #pragma unroll
    for (int off = 16; off > 0; off >>= 1)
        local += __shfl_down_sync(0xffffffffu, local, off);
    if (lane == 0) swred[wid] = local;
    __syncthreads();
    if (wid == 0) {
        double v = (lane < NWARP) ? swred[lane] : 0.0;
        #pragma unroll
        for (int off = 16; off > 0; off >>= 1)
            v += __shfl_down_sync(0xffffffffu, v, off);
        if (lane == 0) atomicAdd(&g_acc1, v);
    }

    // ---------------- Grid barrier (7 blocks, all co-resident) --------------
    __threadfence();
    __syncthreads();
    if (tid == 0) {
        atomicAdd(&g_done1, 1);
        volatile int* vd = &g_done1;
        while (*vd < nblocks) { __nanosleep(64); }
    }
    __syncthreads();
    __threadfence();

    const int K = g_cnt;

    // ---------------- Phase 2: warp-per-object-cell conf loss ---------------
    double l2 = 0.0;
    const int gwarp  = blockIdx.x * NWARP + wid;
    const int nwarps = nblocks * NWARP;
    for (int c = gwarp; c < K; c += nwarps) {
        float bx1 = g_px1[c], by1 = g_py1[c], bx2 = g_px2[c], by2 = g_py2[c];
        float ba  = g_pa[c],  bpc = g_pc[c];
        float best = -1.0f;
        #pragma unroll 4
        for (int j = lane; j < K; j += 32) {
            float iw = fminf(bx2, g_tx2[j]) - fmaxf(bx1, g_tx1[j]);
            float ih = fminf(by2, g_ty2[j]) - fmaxf(by1, g_ty1[j]);
            iw = fmaxf(iw, 0.0f);
            ih = fmaxf(ih, 0.0f);
            float inter = iw * ih;
            float iou = __fdividef(inter, ba + g_ta[j] - inter + EPS_IOU);
            best = fmaxf(best, iou);
        }
        #pragma unroll
        for (int off = 16; off > 0; off >>= 1)
            best = fmaxf(best, __shfl_xor_sync(0xffffffffu, best, off));
        if (lane == 0) {
            float d = bpc - best;
            l2 += (double)(d * d);
        }
    }

    // block reduce phase-2 losses -> single double atomic
    if (lane == 0) swred[wid] = l2;
    __syncthreads();
    if (wid == 0) {
        double v = (lane < NWARP) ? swred[lane] : 0.0;
        #pragma unroll
        for (int off = 16; off > 0; off >>= 1)
            v += __shfl_down_sync(0xffffffffu, v, off);
        if (lane == 0) atomicAdd(&g_acc2, v);
    }

    // ---------------- Last block finalizes + resets --------------------------
    __threadfence();
    __syncthreads();
    if (tid == 0) {
        if (atomicAdd(&g_done2, 1) == nblocks - 1) {
            out[0] = (float)((g_acc1 + g_acc2) * (double)invB);
            g_acc1  = 0.0;   // reset for next graph replay
            g_acc2  = 0.0;
            g_cnt   = 0;
            g_done1 = 0;
            g_done2 = 0;
        }
    }
}

extern "C" void kernel_launch(void* const* d_in, const int* in_sizes, int n_in,
                              void* d_out, int out_size) {
    const float* pred = (const float*)d_in[0];
    const float* targ = (const float*)d_in[1];
    float* out = (float*)d_out;

    int total = in_sizes[0];           // B * S * S * N
    int M = total / NCH;               // 6272 cells
    int B = M / (SS * SS);
    float invB = 1.0f / (float)B;

    int nblocks = (M + TPB - 1) / TPB; // 7  (co-resident: 7 << #SMs)
    k_yolo_coop<<<nblocks, TPB>>>(pred, targ, out, M, nblocks, invB);
}